// round 17
// baseline (speedup 1.0000x reference)
#include <cuda_runtime.h>
#include <math.h>
#include <stdint.h>

// ---------------- problem constants ----------------
#define S_   8192
#define H_   16
#define D_   128
#define HD_  2048
#define C_   12
#define MP_  12
#define CTX_ 24
#define POS_ 13
#define NBLK_ 683          // ceil(8192/12)
#define NB4_  171          // ceil(683/4)
#define KSPLIT_ 16

// scratch (device globals: allocation-free rule)
__device__ float g_q[(size_t)S_ * HD_];
__device__ float g_k[(size_t)S_ * HD_];
__device__ float g_v[(size_t)S_ * HD_];
__device__ float g_ctx[(size_t)S_ * HD_];
__device__ float g_wt0[(size_t)HD_ * HD_];
__device__ float g_wt1[(size_t)HD_ * HD_];
__device__ float g_wt2[(size_t)HD_ * HD_];
__device__ float g_wt3[(size_t)HD_ * HD_];
__device__ float g_relk[(size_t)POS_ * HD_];
__device__ float g_relpart[(size_t)KSPLIT_ * POS_ * HD_];

// ---------------- small PTX helpers ----------------
__device__ __forceinline__ uint32_t smem_u32(const void* p) {
    uint32_t a;
    asm("{ .reg .u64 t; cvta.to.shared.u64 t, %1; cvt.u32.u64 %0, t; }" : "=r"(a) : "l"(p));
    return a;
}
__device__ __forceinline__ float rtf32(float x) {
    uint32_t r;
    asm("cvt.rna.tf32.f32 %0, %1;" : "=r"(r) : "f"(x));
    return __uint_as_float(r);
}
__device__ __forceinline__ uint32_t u_rtf32(float x) {
    uint32_t r;
    asm("cvt.rna.tf32.f32 %0, %1;" : "=r"(r) : "f"(x));
    return r;
}
__device__ __forceinline__ void cp_async16(uint32_t dst, const void* src) {
    asm volatile("cp.async.cg.shared.global [%0], [%1], 16;" :: "r"(dst), "l"(src) : "memory");
}
__device__ __forceinline__ void cp_commit() {
    asm volatile("cp.async.commit_group;" ::: "memory");
}
__device__ __forceinline__ void mma_tf32(float* d, const uint32_t* a, const uint32_t* b) {
    asm volatile("mma.sync.aligned.m16n8k8.row.col.f32.tf32.tf32.f32 "
                 "{%0,%1,%2,%3}, {%4,%5,%6,%7}, {%8,%9}, {%0,%1,%2,%3};"
                 : "+f"(d[0]), "+f"(d[1]), "+f"(d[2]), "+f"(d[3])
                 : "r"(a[0]), "r"(a[1]), "r"(a[2]), "r"(a[3]), "r"(b[0]), "r"(b[1]));
}

// ---------------- tf32 mma.sync GEMM ----------------
// C[M,2048] = A[M,2048] @ W[2048,2048]   (W row-major [K][N])
// CTA 128x128, BK=32, 3-stage cp.async, 8 warps (4 m x 2 n), warp tile 32x64.
// RND: apply cvt.rna.tf32 to A fragments (A may be raw fp32).
#define BM_  128
#define BN_  128
#define BK_  32
#define NST_ 3
#define ASTR_ 36
#define BSTR_ 136
#define A_SZ_ (BM_ * ASTR_)             // 4608 floats
#define B_SZ_ (BK_ * BSTR_)             // 4352 floats
#define STG_SZ_ (A_SZ_ + B_SZ_)         // 8960 floats
#define GSMEM_ (NST_ * STG_SZ_ * 4)     // 107520 bytes
#define NIT_  (HD_ / BK_)               // 64

struct GemmBody {
    const float* agp;
    const float* wgp;
    uint32_t sb;
    int arow0, acol0, brow0, bcol0;

    __device__ __forceinline__ void stage_load(int s, int k0) const {
        uint32_t as = sb + (uint32_t)(s * STG_SZ_) * 4;
        uint32_t bs = as + A_SZ_ * 4;
#pragma unroll
        for (int i = 0; i < 4; i++)
            cp_async16(as + (((arow0 + i * 32) * ASTR_ + acol0) * 4),
                       agp + (size_t)(i * 32) * HD_ + k0);
#pragma unroll
        for (int i = 0; i < 4; i++)
            cp_async16(bs + (((brow0 + i * 8) * BSTR_ + bcol0) * 4),
                       wgp + (size_t)(k0 + i * 8) * HD_);
    }
};

template <bool RND>
__global__ void __launch_bounds__(256, 2)
gemm_mma_qkv(const float* __restrict__ A,
             const float* __restrict__ W0, const float* __restrict__ W1,
             const float* __restrict__ W2,
             float* __restrict__ C0, float* __restrict__ C1, float* __restrict__ C2)
{
    extern __shared__ float smem[];
    const int tid  = threadIdx.x;
    const int warp = tid >> 5;
    const int lane = tid & 31;
    const int wm   = warp & 3;
    const int wn   = warp >> 2;
    const int brow = blockIdx.y * BM_;
    const int bcol = blockIdx.x * BN_;
    const int r    = lane >> 2;
    const int c    = lane & 3;

    const float* W = (blockIdx.z == 0) ? W0 : (blockIdx.z == 1) ? W1 : W2;
    float* Cc      = (blockIdx.z == 0) ? C0 : (blockIdx.z == 1) ? C1 : C2;

    GemmBody gb;
    gb.arow0 = tid >> 3;
    gb.acol0 = (tid & 7) * 4;
    gb.brow0 = tid >> 5;
    gb.bcol0 = (tid & 31) * 4;
    gb.agp = A + (size_t)(brow + gb.arow0) * HD_ + gb.acol0;
    gb.wgp = W + (size_t)gb.brow0 * HD_ + bcol + gb.bcol0;
    gb.sb  = smem_u32(smem);

    float acc[2][8][4];
#pragma unroll
    for (int i = 0; i < 2; i++)
#pragma unroll
        for (int j = 0; j < 8; j++)
#pragma unroll
            for (int e = 0; e < 4; e++) acc[i][j][e] = 0.f;

#pragma unroll
    for (int s = 0; s < NST_ - 1; s++) {
        gb.stage_load(s, s * BK_);
        cp_commit();
    }

    int sc = 0;
    int sl = NST_ - 1;
    for (int it = 0; it < NIT_; it++) {
        asm volatile("cp.async.wait_group %0;" :: "n"(NST_ - 2) : "memory");
        __syncthreads();
        if (it + NST_ - 1 < NIT_)
            gb.stage_load(sl, (it + NST_ - 1) * BK_);
        cp_commit();

        const float* As = smem + sc * STG_SZ_;
        const float* Bs = As + A_SZ_;

#pragma unroll
        for (int ks = 0; ks < 4; ks++) {
            const int kc = c + ks * 8;
            uint32_t af[2][4];
#pragma unroll
            for (int i = 0; i < 2; i++) {
                const int row = wm * 32 + i * 16 + r;
                float a0 = As[row * ASTR_ + kc];
                float a1 = As[(row + 8) * ASTR_ + kc];
                float a2 = As[row * ASTR_ + kc + 4];
                float a3 = As[(row + 8) * ASTR_ + kc + 4];
                af[i][0] = RND ? u_rtf32(a0) : __float_as_uint(a0);
                af[i][1] = RND ? u_rtf32(a1) : __float_as_uint(a1);
                af[i][2] = RND ? u_rtf32(a2) : __float_as_uint(a2);
                af[i][3] = RND ? u_rtf32(a3) : __float_as_uint(a3);
            }
            uint32_t bf[8][2];
#pragma unroll
            for (int j = 0; j < 8; j++) {
                const int n = wn * 64 + j * 8 + r;
                bf[j][0] = __float_as_uint(Bs[kc * BSTR_ + n]);
                bf[j][1] = __float_as_uint(Bs[(kc + 4) * BSTR_ + n]);
            }
#pragma unroll
            for (int i = 0; i < 2; i++)
#pragma unroll
                for (int j = 0; j < 8; j++)
                    mma_tf32(acc[i][j], af[i], bf[j]);
        }
        sc = (sc == NST_ - 1) ? 0 : sc + 1;
        sl = (sl == NST_ - 1) ? 0 : sl + 1;
    }

#pragma unroll
    for (int i = 0; i < 2; i++) {
        const int row0 = brow + wm * 32 + i * 16 + r;
#pragma unroll
        for (int j = 0; j < 8; j++) {
            const int col = bcol + wn * 64 + j * 8 + c * 2;
            *(float2*)(Cc + (size_t)row0 * HD_ + col)       = make_float2(acc[i][j][0], acc[i][j][1]);
            *(float2*)(Cc + (size_t)(row0 + 8) * HD_ + col) = make_float2(acc[i][j][2], acc[i][j][3]);
        }
    }
}

// ---------------- tf32 rounding for the 4 weights ----------------
#define NW4_ (HD_ * HD_ / 4)
__global__ void round_w(const float* __restrict__ wq, const float* __restrict__ wk,
                        const float* __restrict__ wv, const float* __restrict__ wp,
                        float* __restrict__ w0, float* __restrict__ w1,
                        float* __restrict__ w2, float* __restrict__ w3)
{
    const int total = 4 * NW4_;
    for (int i = blockIdx.x * blockDim.x + threadIdx.x; i < total;
         i += gridDim.x * blockDim.x) {
        int w = i / NW4_;
        int off = i - w * NW4_;
        const float4* src = (const float4*)((w == 0) ? wq : (w == 1) ? wk : (w == 2) ? wv : wp);
        float4* dst = (float4*)((w == 0) ? w0 : (w == 1) ? w1 : (w == 2) ? w2 : w3);
        float4 v = src[off];
        v.x = rtf32(v.x); v.y = rtf32(v.y); v.z = rtf32(v.z); v.w = rtf32(v.w);
        dst[off] = v;
    }
}

// ---------------- rel-position GEMM (split-K, exact fp32) ----------------
__global__ void relgemm_part(const float* __restrict__ pe, const float* __restrict__ W,
                             float* __restrict__ part)
{
    __shared__ float pes[POS_][128];
    const int tid = threadIdx.x;
    const int nb = blockIdx.x, ks = blockIdx.y;
    for (int idx = tid; idx < POS_ * 128; idx += 128) {
        int m = idx >> 7, kk = idx & 127;
        pes[m][kk] = pe[(size_t)m * HD_ + ks * 128 + kk];
    }
    __syncthreads();
    const int n = nb * 128 + tid;
    float acc[POS_];
#pragma unroll
    for (int m = 0; m < POS_; m++) acc[m] = 0.f;
    for (int kk = 0; kk < 128; kk++) {
        float w = W[(size_t)(ks * 128 + kk) * HD_ + n];
#pragma unroll
        for (int m = 0; m < POS_; m++) acc[m] = fmaf(pes[m][kk], w, acc[m]);
    }
#pragma unroll
    for (int m = 0; m < POS_; m++)
        part[((size_t)ks * POS_ + m) * HD_ + n] = acc[m];
}

__global__ void relgemm_reduce(const float* __restrict__ part, float* __restrict__ relk)
{
    int i = blockIdx.x * blockDim.x + threadIdx.x;
    if (i < POS_ * HD_) {
        float s = 0.f;
#pragma unroll
        for (int ks = 0; ks < KSPLIT_; ks++) s += part[(size_t)ks * POS_ * HD_ + i];
        relk[i] = s;
    }
}

// ---------------- chunked attention: block = (4 chunks, 1 head) ----------------
// Register-tiled scores (4x4 -> 0.5 LDS/FMA) + register-cached V in AV phase.
// Dynamic smem layout (floats):
#define AOF_Q  0                       // qs [48][129]
#define AOF_K  6192                    // ks [60][129]
#define AOF_V  13932                   // vs [60][129]
#define AOF_R  21672                   // rk [13][129]
#define AOF_AC 23349                   // ac [48][25]
#define AOF_BD 24549                   // bd [48][14]
#define AOF_PR 25224                   // pr [48][28]  (float4-aligned rows)
#define ATTN_SMEM ((25224 + 48 * 28) * 4)   // 106272 bytes

__global__ __launch_bounds__(128)
void attn_kernel(const float* __restrict__ q, const float* __restrict__ k,
                 const float* __restrict__ v, const float* __restrict__ relk,
                 const float* __restrict__ pds, float* __restrict__ ctx)
{
    extern __shared__ float sm[];
    float* qs = sm + AOF_Q;
    float* ks = sm + AOF_K;
    float* vs = sm + AOF_V;
    float* rk = sm + AOF_R;
    float* ac = sm + AOF_AC;
    float* bd = sm + AOF_BD;
    float* pr = sm + AOF_PR;

    const int bx  = blockIdx.x;        // 4-chunk group
    const int h   = blockIdx.y;
    const int tid = threadIdx.x;       // == d in load/output phases
    const int t0  = bx * 48;           // first query position of the group

    // loads (thread owns column d = tid)
    const float qscale = 0.08838834764831845f * 1.4426950408889634f
                       * log1pf(expf(pds[tid]));
#pragma unroll 4
    for (int r = 0; r < 48; r++) {
        int t = t0 + r;
        qs[r * 129 + tid] = (t < S_) ? q[(size_t)t * HD_ + h * D_ + tid] * qscale : 0.f;
    }
#pragma unroll 4
    for (int i = 0; i < 60; i++) {
        int p = t0 - MP_ + i;
        bool ok = (p >= 0) && (p < S_);
        size_t off = (size_t)p * HD_ + h * D_ + tid;
        ks[i * 129 + tid] = ok ? k[off] : 0.f;
        vs[i * 129 + tid] = ok ? v[off] : 0.f;
    }
#pragma unroll
    for (int p = 0; p < POS_; p++)
        rk[p * 129 + tid] = relk[(size_t)p * HD_ + h * D_ + tid];
    __syncthreads();

    // scores: ac tiles 4x4 (threads 0..71), bd tiles 4x4 (threads 72..119)
    if (tid < 72) {
        const int c0 = (tid / 6) * 4;          // 4-row group (never crosses a chunk)
        const int j0 = (tid % 6) * 4;
        const int kb = (c0 / C_) * C_;         // key-row base for this chunk
        float acc[4][4];
#pragma unroll
        for (int i = 0; i < 4; i++)
#pragma unroll
            for (int j = 0; j < 4; j++) acc[i][j] = 0.f;
        for (int dd = 0; dd < D_; dd++) {
            float qv[4], kv[4];
#pragma unroll
            for (int i = 0; i < 4; i++) qv[i] = qs[(c0 + i) * 129 + dd];
#pragma unroll
            for (int j = 0; j < 4; j++) kv[j] = ks[(kb + j0 + j) * 129 + dd];
#pragma unroll
            for (int i = 0; i < 4; i++)
#pragma unroll
                for (int j = 0; j < 4; j++)
                    acc[i][j] = fmaf(qv[i], kv[j], acc[i][j]);
        }
#pragma unroll
        for (int i = 0; i < 4; i++)
#pragma unroll
            for (int j = 0; j < 4; j++)
                ac[(c0 + i) * 25 + j0 + j] = acc[i][j];
    } else if (tid < 120) {
        const int tt = tid - 72;
        const int c0 = (tt / 4) * 4;
        const int p0 = (tt % 4) * 4;
        const int pn = (p0 + 4 <= POS_) ? 4 : (POS_ - p0);   // 4,4,4,1
        float acc[4][4];
#pragma unroll
        for (int i = 0; i < 4; i++)
#pragma unroll
            for (int j = 0; j < 4; j++) acc[i][j] = 0.f;
        for (int dd = 0; dd < D_; dd++) {
            float qv[4], rv[4];
#pragma unroll
            for (int i = 0; i < 4; i++) qv[i] = qs[(c0 + i) * 129 + dd];
#pragma unroll
            for (int j = 0; j < 4; j++)
                rv[j] = (j < pn) ? rk[(p0 + j) * 129 + dd] : 0.f;
#pragma unroll
            for (int i = 0; i < 4; i++)
#pragma unroll
                for (int j = 0; j < 4; j++)
                    acc[i][j] = fmaf(qv[i], rv[j], acc[i][j]);
        }
#pragma unroll
        for (int i = 0; i < 4; i++)
            for (int j = 0; j < pn; j++)
                bd[(c0 + i) * 14 + p0 + j] = acc[i][j];
    }
    __syncthreads();

    // rel-shift + softcap + softmax (thread per query row, 48 active)
    if (tid < 48) {
        const int row = tid;
        const int cc  = row / C_;
        const int c   = row % C_;
        float sr[CTX_];
        float m = -1e30f;
#pragma unroll
        for (int j = 0; j < CTX_; j++) {
            int i  = c * CTX_ + j;
            int cp = i / (CTX_ + 1);
            int pp = i % (CTX_ + 1);
            float val = ac[row * 25 + j]
                      + ((pp < POS_) ? bd[(cc * C_ + cp) * 14 + pp] : 0.f);
            val = tanhf(val * 0.02f) * 50.f;
            sr[j] = val;
            m = fmaxf(m, val);
        }
        float sum = 0.f;
#pragma unroll
        for (int j = 0; j < CTX_; j++) { sr[j] = expf(sr[j] - m); sum += sr[j]; }
        float inv = 1.f / sum;
#pragma unroll
        for (int j = 0; j < CTX_; j++) pr[row * 28 + j] = sr[j] * inv;
    }
    __syncthreads();

    // output: thread d; V rows cached in registers per chunk; pr via broadcast float4
#pragma unroll
    for (int cc = 0; cc < 4; cc++) {
        float vv[CTX_];
#pragma unroll
        for (int j = 0; j < CTX_; j++) vv[j] = vs[(cc * C_ + j) * 129 + tid];
#pragma unroll
        for (int c = 0; c < C_; c++) {
            int t = t0 + cc * C_ + c;
            if (t >= S_) break;
            const int row = cc * C_ + c;
            const float4* p4 = (const float4*)(pr + row * 28);
            float o = 0.f;
#pragma unroll
            for (int j4 = 0; j4 < 6; j4++) {
                float4 pv = p4[j4];
                o = fmaf(pv.x, vv[j4 * 4 + 0], o);
                o = fmaf(pv.y, vv[j4 * 4 + 1], o);
                o = fmaf(pv.z, vv[j4 * 4 + 2], o);
                o = fmaf(pv.w, vv[j4 * 4 + 3], o);
            }
            ctx[(size_t)t * HD_ + h * D_ + tid] = rtf32(o);  // pre-round for post-GEMM
        }
    }
}

// ---------------- launch ----------------
extern "C" void kernel_launch(void* const* d_in, const int* in_sizes, int n_in,
                              void* d_out, int out_size)
{
    const float* x     = (const float*)d_in[0];
    const float* pe    = (const float*)d_in[1];
    const float* Wq    = (const float*)d_in[2];
    const float* Wk    = (const float*)d_in[3];
    const float* Wv    = (const float*)d_in[4];
    const float* Wrel  = (const float*)d_in[5];
    const float* Wpost = (const float*)d_in[6];
    const float* pds   = (const float*)d_in[7];
    float* out = (float*)d_out;

    float *pq, *pk, *pv, *pctx, *pw0, *pw1, *pw2, *pw3, *prelk, *ppart;
    cudaGetSymbolAddress((void**)&pq,    g_q);
    cudaGetSymbolAddress((void**)&pk,    g_k);
    cudaGetSymbolAddress((void**)&pv,    g_v);
    cudaGetSymbolAddress((void**)&pctx,  g_ctx);
    cudaGetSymbolAddress((void**)&pw0,   g_wt0);
    cudaGetSymbolAddress((void**)&pw1,   g_wt1);
    cudaGetSymbolAddress((void**)&pw2,   g_wt2);
    cudaGetSymbolAddress((void**)&pw3,   g_wt3);
    cudaGetSymbolAddress((void**)&prelk, g_relk);
    cudaGetSymbolAddress((void**)&ppart, g_relpart);

    cudaFuncSetAttribute(gemm_mma_qkv<true>,  cudaFuncAttributeMaxDynamicSharedMemorySize, GSMEM_);
    cudaFuncSetAttribute(gemm_mma_qkv<false>, cudaFuncAttributeMaxDynamicSharedMemorySize, GSMEM_);
    cudaFuncSetAttribute(attn_kernel, cudaFuncAttributeMaxDynamicSharedMemorySize, ATTN_SMEM);

    // 1-2: rel-position GEMM (tiny, split-K, exact fp32)
    relgemm_part<<<dim3(HD_ / 128, KSPLIT_), 128>>>(pe, Wrel, ppart);
    relgemm_reduce<<<(POS_ * HD_ + 255) / 256, 256>>>(ppart, prelk);

    // 3: tf32-round the 4 weight matrices
    round_w<<<4096, 256>>>(Wq, Wk, Wv, Wpost, pw0, pw1, pw2, pw3);

    // 4: fused QKV GEMM (A = raw x, rounded in-fragment)
    dim3 gq(HD_ / BN_, S_ / BM_, 3);   // (16, 64, 3)
    gemm_mma_qkv<true><<<gq, 256, GSMEM_>>>(x, pw0, pw1, pw2, pq, pk, pv);

    // 5: chunked attention (4 chunks per block)
    attn_kernel<<<dim3(NB4_, H_), 128, ATTN_SMEM>>>(pq, pk, pv, prelk, pds, pctx);

    // 6: post GEMM (A = pctx, already rounded by attn)
    dim3 gp(HD_ / BN_, S_ / BM_, 1);
    gemm_mma_qkv<false><<<gp, 256, GSMEM_>>>(pctx, pw3, pw3, pw3, out, out, out);
}